// round 10
// baseline (speedup 1.0000x reference)
#include <cuda_runtime.h>
#include <cuda_fp16.h>
#include <cstdint>

#define Bn 32
#define Gn 512
#define Dn 128
#define Hn 4
#define NORMF 0.17677669529663687f   // 1/sqrt(32)

// Scratch (device globals — no allocation allowed)
__device__ float g_M[4][Bn][Hn][Dn];        // [map: p1,p2,d1,d2][b][h][d]
__device__ uint32_t g_Ah2 [Bn * Gn * 16];   // fc1 i-side partial, half2, perm-k
__device__ uint32_t g_Bvh2[Bn * Gn * 16];   // fc1 j-side partial + b1, half2, perm-k

__constant__ float cFC1W[16][32];
__constant__ float cFC1B[32];
__constant__ float cB2[32];
__constant__ float cW3[32];
__constant__ float cB3[1];

// -------------------------------------------------------------------------
// prep1: grid (Hn, Bn). Block (hh, b): Q[hh] = q @ Wq[hh] (32 k), then
// M[map][b][hh][d] = NORM * sum_k Q·Wk[hh,d,k].
// -------------------------------------------------------------------------
__global__ void __launch_bounds__(512) prep1(const float* __restrict__ h,
                      const int* __restrict__ pp,
                      const int* __restrict__ pd,
                      const float* __restrict__ Wq1,
                      const float* __restrict__ Wk1,
                      const float* __restrict__ Wq2,
                      const float* __restrict__ Wk2) {
    int hh = blockIdx.x;
    int b  = blockIdx.y;
    int t  = threadIdx.x;   // 0..511
    __shared__ float shp[Dn], shd[Dn];
    __shared__ float sQp[16][4][32];   // [d-segment][map][k]
    __shared__ float sQ[4][32];

    int ip = pp[b], id = pd[b];
    if (t < Dn)            shp[t]      = h[(b * Gn + ip) * Dn + t];
    else if (t < 2 * Dn)   shd[t - Dn] = h[(b * Gn + id) * Dn + (t - Dn)];
    __syncthreads();

    {   // phase A: 16 segments of 8 d each
        int k = t & 31, seg = t >> 5;
        float q_p1 = 0.f, q_p2 = 0.f, q_d1 = 0.f, q_d2 = 0.f;
        #pragma unroll
        for (int dd = 0; dd < 8; dd++) {
            int d = seg * 8 + dd;
            float w1 = Wq1[(hh * Dn + d) * 32 + k];
            float w2 = Wq2[(hh * Dn + d) * 32 + k];
            float xp = shp[d], xd = shd[d];
            q_p1 = fmaf(xp, w1, q_p1);
            q_p2 = fmaf(xp, w2, q_p2);
            q_d1 = fmaf(xd, w1, q_d1);
            q_d2 = fmaf(xd, w2, q_d2);
        }
        sQp[seg][0][k] = q_p1;
        sQp[seg][1][k] = q_p2;
        sQp[seg][2][k] = q_d1;
        sQp[seg][3][k] = q_d2;
    }
    __syncthreads();
    if (t < 128) {
        int m = t >> 5, k = t & 31;
        float s = 0.f;
        #pragma unroll
        for (int seg = 0; seg < 16; seg++) s += sQp[seg][m][k];
        sQ[m][k] = s;
    }
    __syncthreads();

    {   // phase B: one (d, map) per thread
        int d = t >> 2, m = t & 3;
        const float* wk = (m & 1) ? Wk2 : Wk1;   // maps 0,2 -> Wk1; 1,3 -> Wk2
        const float4* wr = (const float4*)&wk[(hh * Dn + d) * 32];
        float acc = 0.f;
        #pragma unroll
        for (int i4 = 0; i4 < 8; i4++) {
            float4 a = __ldg(wr + i4);
            int k0 = i4 * 4;
            acc = fmaf(sQ[m][k0 + 0], a.x, acc);
            acc = fmaf(sQ[m][k0 + 1], a.y, acc);
            acc = fmaf(sQ[m][k0 + 2], a.z, acc);
            acc = fmaf(sQ[m][k0 + 3], a.w, acc);
        }
        g_M[m][b][hh][d] = acc * NORMF;
    }
}

// -------------------------------------------------------------------------
// prep2: 256 threads, 128 g per block; each g has 2 threads splitting the
// d-reduction, then half0 folds the A side and half1 folds the Bv side.
// Output: packed half2 in fragment-permuted k order.
// -------------------------------------------------------------------------
__global__ void __launch_bounds__(256) prep2(const float* __restrict__ h,
                                             const int* __restrict__ rec) {
    int b  = blockIdx.y;
    int t  = threadIdx.x;
    int gl = t & 127;          // g-lane
    int half = t >> 7;         // 0 or 1
    int g  = blockIdx.x * 128 + gl;

    __shared__ float sM[4][Hn][Dn];       // 8KB
    __shared__ float sX[128][8];          // partner's u (from half1)
    __shared__ float sY[128][8];          // half0's v  (to half1)

    for (int idx = t; idx < 4 * Hn * Dn; idx += 256) {
        int w = idx >> 9;
        int r = idx & 511;
        (&sM[0][0][0])[idx] = (&g_M[0][0][0][0])[(w * Bn + b) * (Hn * Dn) + r];
    }
    __syncthreads();

    int nb = rec[b * Gn + g];
    const float4* hrow = (const float4*)(h + (b * Gn + g) * Dn)  + half * 16;
    const float4* nrow = (const float4*)(h + (b * Gn + nb) * Dn) + half * 16;

    float u[8], v[8];
    #pragma unroll
    for (int l = 0; l < 8; l++) { u[l] = 0.f; v[l] = 0.f; }

    #pragma unroll 4
    for (int d4 = 0; d4 < 16; d4++) {
        float4 xv = __ldg(hrow + d4);
        float4 yv = __ldg(nrow + d4);
        float xs[4] = {xv.x, xv.y, xv.z, xv.w};
        float ys[4] = {yv.x, yv.y, yv.z, yv.w};
        #pragma unroll
        for (int r = 0; r < 4; r++) {
            int d = half * 64 + d4 * 4 + r;
            #pragma unroll
            for (int hh = 0; hh < Hn; hh++) {
                u[hh]     = fmaf(xs[r], sM[0][hh][d], u[hh]);
                u[4 + hh] = fmaf(ys[r], sM[1][hh][d], u[4 + hh]);
                v[hh]     = fmaf(xs[r], sM[2][hh][d], v[hh]);
                v[4 + hh] = fmaf(ys[r], sM[3][hh][d], v[4 + hh]);
            }
        }
    }
    if (half == 1) {
        #pragma unroll
        for (int l = 0; l < 8; l++) sX[gl][l] = u[l];
    } else {
        #pragma unroll
        for (int l = 0; l < 8; l++) sY[gl][l] = v[l];
    }
    __syncthreads();

    float z[8];
    if (half == 0) {
        #pragma unroll
        for (int l = 0; l < 8; l++) z[l] = u[l] + sX[gl][l];   // full u
    } else {
        #pragma unroll
        for (int l = 0; l < 8; l++) z[l] = sY[gl][l] + v[l];   // full v
    }

    float res[32];
    const float* Wslice = half ? &cFC1W[8][0] : &cFC1W[0][0];
    #pragma unroll
    for (int k = 0; k < 32; k++) {
        float a = half ? cFC1B[k] : 0.f;
        #pragma unroll
        for (int l = 0; l < 8; l++)
            a = fmaf(z[l], Wslice[l * 32 + k], a);
        res[k] = a;
    }

    uint32_t pk[16];
    #pragma unroll
    for (int m = 0; m < 16; m++) {
        int c = m >> 3, rem = m & 7, qq = rem >> 1, s = rem & 1;
        int k0 = 16 * c + 2 * qq + 8 * s;
        __half2 hp = __floats2half2_rn(res[k0], res[k0 + 1]);
        pk[m] = *(uint32_t*)&hp;
    }
    uint4* dst = half ? (uint4*)&g_Bvh2[(b * Gn + g) * 16]
                      : (uint4*)&g_Ah2 [(b * Gn + g) * 16];
    #pragma unroll
    for (int c4 = 0; c4 < 4; c4++)
        dst[c4] = make_uint4(pk[4*c4], pk[4*c4+1], pk[4*c4+2], pk[4*c4+3]);
}

// -------------------------------------------------------------------------
// mlp_mma: fc2 via mma m16n8k16 fp16 (f32 acc, bias pre-init), 8 HMMA/tile.
// fc3 on scalar fma/alu pipes (hidden under HMMA stalls). 2 tiles/iter ILP.
// -------------------------------------------------------------------------
#define BV_STRIDE 20   // uint32 per smem row (80B, 16B-aligned)

__global__ void __launch_bounds__(256, 2) mlp_mma(const float* __restrict__ W2,
                                                  float* __restrict__ out) {
    extern __shared__ uint32_t sBv2[];   // [512][BV_STRIDE]
    const int t = threadIdx.x;
    const int w = t >> 5;
    const int lane = t & 31;
    const int q = lane & 3;          // threadID_in_group
    const int r = lane >> 2;         // groupID
    const int b = blockIdx.y;
    const int i = blockIdx.x * 8 + w;

    // ---- stage Bvh[b] into smem ----
    {
        const uint4* src = (const uint4*)&g_Bvh2[b * Gn * 16];
        for (int idx = t; idx < Gn * 4; idx += 256) {
            int j = idx >> 2, c4 = idx & 3;
            uint4 v = __ldg(src + idx);
            *(uint4*)&sBv2[j * BV_STRIDE + c4 * 4] = v;
        }
    }

    // ---- loop-invariant per-thread data ----
    uint2 Ah[2];
    {
        const uint32_t* ar = &g_Ah2[(b * Gn + i) * 16];
        Ah[0] = *(const uint2*)&ar[2 * q];
        Ah[1] = *(const uint2*)&ar[8 + 2 * q];
    }
    uint32_t wb[4][2][2];
    #pragma unroll
    for (int nbk = 0; nbk < 4; nbk++)
        #pragma unroll
        for (int c = 0; c < 2; c++) {
            int n = 8 * nbk + r;
            __half2 w0 = __floats2half2_rn(__ldg(&W2[(16*c + 2*q)     * 32 + n]),
                                           __ldg(&W2[(16*c + 2*q + 1) * 32 + n]));
            __half2 w1 = __floats2half2_rn(__ldg(&W2[(16*c + 2*q + 8) * 32 + n]),
                                           __ldg(&W2[(16*c + 2*q + 9) * 32 + n]));
            wb[nbk][c][0] = *(uint32_t*)&w0;
            wb[nbk][c][1] = *(uint32_t*)&w1;
        }
    float b2v[4][2], w3v[4][2];
    #pragma unroll
    for (int nbk = 0; nbk < 4; nbk++) {
        b2v[nbk][0] = cB2[8 * nbk + 2 * q];
        b2v[nbk][1] = cB2[8 * nbk + 2 * q + 1];
        w3v[nbk][0] = cW3[8 * nbk + 2 * q];
        w3v[nbk][1] = cW3[8 * nbk + 2 * q + 1];
    }
    const float b3 = cB3[0];
    const __half2 hz = __float2half2_rn(0.f);
    __syncthreads();

    float* outrow = out + ((size_t)(b * Gn + i)) * Gn;
    const uint32_t* bvlo = sBv2 + r * BV_STRIDE + 2 * q;
    const uint32_t* bvhi = sBv2 + (r + 8) * BV_STRIDE + 2 * q;

    for (int jt = 0; jt < 16; jt++) {
        const int j0 = jt * 32;

        float acc[2][4][4];
        #pragma unroll
        for (int p = 0; p < 2; p++)
            #pragma unroll
            for (int nbk = 0; nbk < 4; nbk++) {
                acc[p][nbk][0] = b2v[nbk][0]; acc[p][nbk][1] = b2v[nbk][1];
                acc[p][nbk][2] = b2v[nbk][0]; acc[p][nbk][3] = b2v[nbk][1];
            }

        // two independent tiles p=0 (rows j0..j0+15) and p=1 (j0+16..j0+31)
        #pragma unroll
        for (int c = 0; c < 2; c++) {
            uint32_t a[2][4];
            #pragma unroll
            for (int p = 0; p < 2; p++) {
                const uint32_t* pl = bvlo + (j0 + 16 * p) * BV_STRIDE;
                const uint32_t* ph = bvhi + (j0 + 16 * p) * BV_STRIDE;
                uint2 rl = *(const uint2*)(pl + 8 * c);
                uint2 rh = *(const uint2*)(ph + 8 * c);
                __half2 av0 = *(__half2*)&Ah[c].x;
                __half2 av1 = *(__half2*)&Ah[c].y;
                __half2 f0 = __hmax2(__hadd2(av0, *(__half2*)&rl.x), hz);
                __half2 f1 = __hmax2(__hadd2(av0, *(__half2*)&rh.x), hz);
                __half2 f2 = __hmax2(__hadd2(av1, *(__half2*)&rl.y), hz);
                __half2 f3 = __hmax2(__hadd2(av1, *(__half2*)&rh.y), hz);
                a[p][0] = *(uint32_t*)&f0; a[p][1] = *(uint32_t*)&f1;
                a[p][2] = *(uint32_t*)&f2; a[p][3] = *(uint32_t*)&f3;
            }
            #pragma unroll
            for (int nbk = 0; nbk < 4; nbk++)
                #pragma unroll
                for (int p = 0; p < 2; p++) {
                    asm volatile(
                        "mma.sync.aligned.m16n8k16.row.col.f32.f16.f16.f32 "
                        "{%0,%1,%2,%3}, {%4,%5,%6,%7}, {%8,%9}, {%0,%1,%2,%3};"
                        : "+f"(acc[p][nbk][0]), "+f"(acc[p][nbk][1]),
                          "+f"(acc[p][nbk][2]), "+f"(acc[p][nbk][3])
                        : "r"(a[p][0]), "r"(a[p][1]), "r"(a[p][2]), "r"(a[p][3]),
                          "r"(wb[nbk][c][0]), "r"(wb[nbk][c][1]));
                }
        }

        // ---- epilogue: scalar relu + w3 dot (fma/alu pipes), shuffle-reduce ----
        #pragma unroll
        for (int p = 0; p < 2; p++) {
            float s0 = 0.f, s1 = 0.f;
            #pragma unroll
            for (int nbk = 0; nbk < 4; nbk++) {
                s0 = fmaf(fmaxf(acc[p][nbk][0], 0.f), w3v[nbk][0], s0);
                s0 = fmaf(fmaxf(acc[p][nbk][1], 0.f), w3v[nbk][1], s0);
                s1 = fmaf(fmaxf(acc[p][nbk][2], 0.f), w3v[nbk][0], s1);
                s1 = fmaf(fmaxf(acc[p][nbk][3], 0.f), w3v[nbk][1], s1);
            }
            s0 += __shfl_xor_sync(0xffffffffu, s0, 1);
            s0 += __shfl_xor_sync(0xffffffffu, s0, 2);
            s1 += __shfl_xor_sync(0xffffffffu, s1, 1);
            s1 += __shfl_xor_sync(0xffffffffu, s1, 2);
            if (q == 0) {
                outrow[j0 + 16 * p + r]     = s0 + b3;
                outrow[j0 + 16 * p + 8 + r] = s1 + b3;
            }
        }
    }
}

// -------------------------------------------------------------------------
extern "C" void kernel_launch(void* const* d_in, const int* in_sizes, int n_in,
                              void* d_out, int out_size) {
    const float* h   = (const float*)d_in[0];
    const int*   pp  = (const int*)  d_in[1];
    const int*   pd  = (const int*)  d_in[2];
    const int*   rec = (const int*)  d_in[3];
    const float* Wq1 = (const float*)d_in[4];
    const float* Wk1 = (const float*)d_in[5];
    const float* Wq2 = (const float*)d_in[6];
    const float* Wk2 = (const float*)d_in[7];
    const float* W2  = (const float*)d_in[10];

    cudaMemcpyToSymbolAsync(cFC1W, d_in[8],  16 * 32 * sizeof(float), 0, cudaMemcpyDeviceToDevice, 0);
    cudaMemcpyToSymbolAsync(cFC1B, d_in[9],  32 * sizeof(float),      0, cudaMemcpyDeviceToDevice, 0);
    cudaMemcpyToSymbolAsync(cB2,   d_in[11], 32 * sizeof(float),      0, cudaMemcpyDeviceToDevice, 0);
    cudaMemcpyToSymbolAsync(cW3,   d_in[12], 32 * sizeof(float),      0, cudaMemcpyDeviceToDevice, 0);
    cudaMemcpyToSymbolAsync(cB3,   d_in[13], 1 * sizeof(float),       0, cudaMemcpyDeviceToDevice, 0);

    const int smem_bytes = Gn * BV_STRIDE * sizeof(uint32_t);   // 40960
    static int smem_set = 0;
    if (!smem_set) {
        cudaFuncSetAttribute(mlp_mma, cudaFuncAttributeMaxDynamicSharedMemorySize, smem_bytes);
        smem_set = 1;
    }

    prep1<<<dim3(Hn, Bn), 512>>>(h, pp, pd, Wq1, Wk1, Wq2, Wk2);
    prep2<<<dim3(4, Bn), 256>>>(h, rec);
    mlp_mma<<<dim3(Gn / 8, Bn), 256, smem_bytes>>>(W2, (float*)d_out);
}

// round 11
// speedup vs baseline: 1.0959x; 1.0959x over previous
#include <cuda_runtime.h>
#include <cuda_fp16.h>
#include <cstdint>

#define Bn 32
#define Gn 512
#define Dn 128
#define Hn 4
#define NORMF 0.17677669529663687f   // 1/sqrt(32)

// Scratch (device globals — no allocation allowed)
__device__ uint32_t g_Ah2 [Bn * Gn * 16];   // fc1 i-side partial, half2, perm-k
__device__ uint32_t g_Bvh2[Bn * Gn * 16];   // fc1 j-side partial + b1, half2, perm-k

// -------------------------------------------------------------------------
// prep (fused): grid (4, Bn), 256 threads. Each block computes the small
// Q-fold and M-fold in smem (redundantly per block — tiny), then the fc1
// fold for its 128 g's. Outputs packed half2 in fragment-permuted k order.
// -------------------------------------------------------------------------
__global__ void __launch_bounds__(256) prep(const float* __restrict__ h,
                                            const int* __restrict__ pp,
                                            const int* __restrict__ pd,
                                            const int* __restrict__ rec,
                                            const float* __restrict__ Wq1,
                                            const float* __restrict__ Wk1,
                                            const float* __restrict__ Wq2,
                                            const float* __restrict__ Wk2,
                                            const float* __restrict__ FC1W,
                                            const float* __restrict__ FC1B) {
    int b   = blockIdx.y;
    int t   = threadIdx.x;
    int gl  = t & 127;
    int half = t >> 7;
    int g   = blockIdx.x * 128 + gl;

    __shared__ float shp[Dn], shd[Dn];
    __shared__ float sQ[4][Hn][32];     // [map][hh][k]
    __shared__ float sM[4][Hn][Dn];     // [map][hh][d]
    __shared__ float sW1[16][32];
    __shared__ float sB1[32];
    __shared__ float sX[128][8];
    __shared__ float sY[128][8];

    int ip = pp[b], id = pd[b];
    if (t < Dn)      shp[t]       = h[(b * Gn + ip) * Dn + t];
    else             shd[t - Dn]  = h[(b * Gn + id) * Dn + (t - Dn)];
    for (int idx = t; idx < 512; idx += 256) ((float*)sW1)[idx] = __ldg(&FC1W[idx]);
    if (t < 32) sB1[t] = __ldg(&FC1B[t]);
    __syncthreads();

    // ---- phase A: Q[map][hh][k] (512 entries, 2/thread) ----
    #pragma unroll
    for (int e0 = 0; e0 < 2; e0++) {
        int e = t + e0 * 256;
        int m = e >> 7, hk = e & 127, hh = hk >> 5, k = hk & 31;
        const float* qv = (m < 2) ? shp : shd;
        const float* Wq = (m & 1) ? Wq2 : Wq1;
        const float* wc = &Wq[(hh * Dn) * 32 + k];
        float acc = 0.f;
        #pragma unroll 8
        for (int d = 0; d < Dn; d++)
            acc = fmaf(qv[d], __ldg(wc + d * 32), acc);
        sQ[m][hh][k] = acc;
    }
    __syncthreads();

    // ---- phase B: M[map][hh][d] (2048 entries, 8/thread) ----
    #pragma unroll
    for (int e0 = 0; e0 < 8; e0++) {
        int e = t + e0 * 256;
        int m = e >> 9, rest = e & 511, hh = rest >> 7, d = rest & 127;
        const float* wk = (m & 1) ? Wk2 : Wk1;
        const float4* wr = (const float4*)&wk[(hh * Dn + d) * 32];
        float acc = 0.f;
        #pragma unroll
        for (int i4 = 0; i4 < 8; i4++) {
            float4 a = __ldg(wr + i4);
            int k0 = i4 * 4;
            acc = fmaf(sQ[m][hh][k0 + 0], a.x, acc);
            acc = fmaf(sQ[m][hh][k0 + 1], a.y, acc);
            acc = fmaf(sQ[m][hh][k0 + 2], a.z, acc);
            acc = fmaf(sQ[m][hh][k0 + 3], a.w, acc);
        }
        sM[m][hh][d] = acc * NORMF;
    }
    __syncthreads();

    // ---- phase C: per-g compat + fc1 fold (2 threads per g) ----
    int nb = rec[b * Gn + g];
    const float4* hrow = (const float4*)(h + (b * Gn + g) * Dn)  + half * 16;
    const float4* nrow = (const float4*)(h + (b * Gn + nb) * Dn) + half * 16;

    float u[8], v[8];
    #pragma unroll
    for (int l = 0; l < 8; l++) { u[l] = 0.f; v[l] = 0.f; }

    #pragma unroll 4
    for (int d4 = 0; d4 < 16; d4++) {
        float4 xv = __ldg(hrow + d4);
        float4 yv = __ldg(nrow + d4);
        float xs[4] = {xv.x, xv.y, xv.z, xv.w};
        float ys[4] = {yv.x, yv.y, yv.z, yv.w};
        #pragma unroll
        for (int r = 0; r < 4; r++) {
            int d = half * 64 + d4 * 4 + r;
            #pragma unroll
            for (int hh = 0; hh < Hn; hh++) {
                u[hh]     = fmaf(xs[r], sM[0][hh][d], u[hh]);
                u[4 + hh] = fmaf(ys[r], sM[1][hh][d], u[4 + hh]);
                v[hh]     = fmaf(xs[r], sM[2][hh][d], v[hh]);
                v[4 + hh] = fmaf(ys[r], sM[3][hh][d], v[4 + hh]);
            }
        }
    }
    if (half == 1) {
        #pragma unroll
        for (int l = 0; l < 8; l++) sX[gl][l] = u[l];
    } else {
        #pragma unroll
        for (int l = 0; l < 8; l++) sY[gl][l] = v[l];
    }
    __syncthreads();

    float z[8];
    if (half == 0) {
        #pragma unroll
        for (int l = 0; l < 8; l++) z[l] = u[l] + sX[gl][l];   // full u
    } else {
        #pragma unroll
        for (int l = 0; l < 8; l++) z[l] = sY[gl][l] + v[l];   // full v
    }

    float res[32];
    const float* Wslice = half ? &sW1[8][0] : &sW1[0][0];
    #pragma unroll
    for (int k = 0; k < 32; k++) {
        float a = half ? sB1[k] : 0.f;
        #pragma unroll
        for (int l = 0; l < 8; l++)
            a = fmaf(z[l], Wslice[l * 32 + k], a);
        res[k] = a;
    }

    uint32_t pk[16];
    #pragma unroll
    for (int m = 0; m < 16; m++) {
        int c = m >> 3, rem = m & 7, qq = rem >> 1, s = rem & 1;
        int k0 = 16 * c + 2 * qq + 8 * s;
        __half2 hp = __floats2half2_rn(res[k0], res[k0 + 1]);
        pk[m] = *(uint32_t*)&hp;
    }
    uint4* dst = half ? (uint4*)&g_Bvh2[(b * Gn + g) * 16]
                      : (uint4*)&g_Ah2 [(b * Gn + g) * 16];
    #pragma unroll
    for (int c4 = 0; c4 < 4; c4++)
        dst[c4] = make_uint4(pk[4*c4], pk[4*c4+1], pk[4*c4+2], pk[4*c4+3]);
}

// -------------------------------------------------------------------------
// mlp_mma (R9 configuration — best known): fc2 via mma m16n8k16 fp16
// (f32 acc, bias pre-init), fc3 via MMA pair, 2 independent j-tiles/iter.
// Weights read once per thread from global (no __constant__, no memcpys).
// -------------------------------------------------------------------------
#define BV_STRIDE 20   // uint32 per smem row (80B, 16B-aligned)

__global__ void __launch_bounds__(256, 2) mlp_mma(const float* __restrict__ W2,
                                                  const float* __restrict__ B2,
                                                  const float* __restrict__ W3,
                                                  const float* __restrict__ B3,
                                                  float* __restrict__ out) {
    extern __shared__ uint32_t sBv2[];   // [512][BV_STRIDE]
    const int t = threadIdx.x;
    const int w = t >> 5;
    const int lane = t & 31;
    const int q = lane & 3;          // threadID_in_group
    const int r = lane >> 2;         // groupID
    const int b = blockIdx.y;
    const int i = blockIdx.x * 8 + w;

    // ---- stage Bvh[b] into smem ----
    {
        const uint4* src = (const uint4*)&g_Bvh2[b * Gn * 16];
        for (int idx = t; idx < Gn * 4; idx += 256) {
            int j = idx >> 2, c4 = idx & 3;
            uint4 v = __ldg(src + idx);
            *(uint4*)&sBv2[j * BV_STRIDE + c4 * 4] = v;
        }
    }

    // ---- loop-invariant per-thread data ----
    uint2 Ah[2];
    {
        const uint32_t* ar = &g_Ah2[(b * Gn + i) * 16];
        Ah[0] = *(const uint2*)&ar[2 * q];
        Ah[1] = *(const uint2*)&ar[8 + 2 * q];
    }
    uint32_t wb[4][2][2];
    #pragma unroll
    for (int nbk = 0; nbk < 4; nbk++)
        #pragma unroll
        for (int c = 0; c < 2; c++) {
            int n = 8 * nbk + r;
            __half2 w0 = __floats2half2_rn(__ldg(&W2[(16*c + 2*q)     * 32 + n]),
                                           __ldg(&W2[(16*c + 2*q + 1) * 32 + n]));
            __half2 w1 = __floats2half2_rn(__ldg(&W2[(16*c + 2*q + 8) * 32 + n]),
                                           __ldg(&W2[(16*c + 2*q + 9) * 32 + n]));
            wb[nbk][c][0] = *(uint32_t*)&w0;
            wb[nbk][c][1] = *(uint32_t*)&w1;
        }
    uint32_t wb3[2][2];
    #pragma unroll
    for (int c = 0; c < 2; c++) {
        __half2 w0 = __floats2half2_rn(__ldg(&W3[16*c + 2*q]),
                                       __ldg(&W3[16*c + 2*q + 1]));
        __half2 w1 = __floats2half2_rn(__ldg(&W3[16*c + 2*q + 8]),
                                       __ldg(&W3[16*c + 2*q + 9]));
        wb3[c][0] = *(uint32_t*)&w0;
        wb3[c][1] = *(uint32_t*)&w1;
    }
    float b2v[4][2];
    #pragma unroll
    for (int nbk = 0; nbk < 4; nbk++) {
        b2v[nbk][0] = __ldg(&B2[8 * nbk + 2 * q]);
        b2v[nbk][1] = __ldg(&B2[8 * nbk + 2 * q + 1]);
    }
    const float b3 = __ldg(&B3[0]);
    const __half2 hz = __float2half2_rn(0.f);
    __syncthreads();

    float* outrow = out + ((size_t)(b * Gn + i)) * Gn;
    const uint32_t* bvlo = sBv2 + r * BV_STRIDE + 2 * q;
    const uint32_t* bvhi = sBv2 + (r + 8) * BV_STRIDE + 2 * q;

    for (int jt = 0; jt < 16; jt++) {
        const int j0 = jt * 32;

        float acc[2][4][4];
        #pragma unroll
        for (int p = 0; p < 2; p++)
            #pragma unroll
            for (int nbk = 0; nbk < 4; nbk++) {
                acc[p][nbk][0] = b2v[nbk][0]; acc[p][nbk][1] = b2v[nbk][1];
                acc[p][nbk][2] = b2v[nbk][0]; acc[p][nbk][3] = b2v[nbk][1];
            }

        // two independent tiles p=0 (rows j0..j0+15) and p=1 (j0+16..j0+31)
        #pragma unroll
        for (int c = 0; c < 2; c++) {
            uint32_t a[2][4];
            #pragma unroll
            for (int p = 0; p < 2; p++) {
                const uint32_t* pl = bvlo + (j0 + 16 * p) * BV_STRIDE;
                const uint32_t* ph = bvhi + (j0 + 16 * p) * BV_STRIDE;
                uint2 rl = *(const uint2*)(pl + 8 * c);
                uint2 rh = *(const uint2*)(ph + 8 * c);
                __half2 av0 = *(__half2*)&Ah[c].x;
                __half2 av1 = *(__half2*)&Ah[c].y;
                __half2 f0 = __hmax2(__hadd2(av0, *(__half2*)&rl.x), hz);
                __half2 f1 = __hmax2(__hadd2(av0, *(__half2*)&rh.x), hz);
                __half2 f2 = __hmax2(__hadd2(av1, *(__half2*)&rl.y), hz);
                __half2 f3 = __hmax2(__hadd2(av1, *(__half2*)&rh.y), hz);
                a[p][0] = *(uint32_t*)&f0; a[p][1] = *(uint32_t*)&f1;
                a[p][2] = *(uint32_t*)&f2; a[p][3] = *(uint32_t*)&f3;
            }
            #pragma unroll
            for (int nbk = 0; nbk < 4; nbk++)
                #pragma unroll
                for (int p = 0; p < 2; p++) {
                    asm volatile(
                        "mma.sync.aligned.m16n8k16.row.col.f32.f16.f16.f32 "
                        "{%0,%1,%2,%3}, {%4,%5,%6,%7}, {%8,%9}, {%0,%1,%2,%3};"
                        : "+f"(acc[p][nbk][0]), "+f"(acc[p][nbk][1]),
                          "+f"(acc[p][nbk][2]), "+f"(acc[p][nbk][3])
                        : "r"(a[p][0]), "r"(a[p][1]), "r"(a[p][2]), "r"(a[p][3]),
                          "r"(wb[nbk][c][0]), "r"(wb[nbk][c][1]));
                }
        }

        // ---- epilogue: relu-pack acc as A-fragments, fc3 via 2 HMMA/tile ----
        float o[2][2];
        #pragma unroll
        for (int p = 0; p < 2; p++) {
            float o0 = b3, o1 = 0.f, o2 = b3, o3 = 0.f;
            #pragma unroll
            for (int c = 0; c < 2; c++) {
                __half2 g0 = __hmax2(__floats2half2_rn(acc[p][2*c][0],   acc[p][2*c][1]),   hz);
                __half2 g1 = __hmax2(__floats2half2_rn(acc[p][2*c][2],   acc[p][2*c][3]),   hz);
                __half2 g2 = __hmax2(__floats2half2_rn(acc[p][2*c+1][0], acc[p][2*c+1][1]), hz);
                __half2 g3 = __hmax2(__floats2half2_rn(acc[p][2*c+1][2], acc[p][2*c+1][3]), hz);
                uint32_t a0 = *(uint32_t*)&g0, a1 = *(uint32_t*)&g1;
                uint32_t a2 = *(uint32_t*)&g2, a3 = *(uint32_t*)&g3;
                asm volatile(
                    "mma.sync.aligned.m16n8k16.row.col.f32.f16.f16.f32 "
                    "{%0,%1,%2,%3}, {%4,%5,%6,%7}, {%8,%9}, {%0,%1,%2,%3};"
                    : "+f"(o0), "+f"(o1), "+f"(o2), "+f"(o3)
                    : "r"(a0), "r"(a1), "r"(a2), "r"(a3),
                      "r"(wb3[c][0]), "r"(wb3[c][1]));
            }
            o[p][0] = o0; o[p][1] = o2;
        }
        if (q == 0) {
            outrow[j0 + r]      = o[0][0];
            outrow[j0 + 8 + r]  = o[0][1];
            outrow[j0 + 16 + r] = o[1][0];
            outrow[j0 + 24 + r] = o[1][1];
        }
    }
}

// -------------------------------------------------------------------------
extern "C" void kernel_launch(void* const* d_in, const int* in_sizes, int n_in,
                              void* d_out, int out_size) {
    const float* h    = (const float*)d_in[0];
    const int*   pp   = (const int*)  d_in[1];
    const int*   pd   = (const int*)  d_in[2];
    const int*   rec  = (const int*)  d_in[3];
    const float* Wq1  = (const float*)d_in[4];
    const float* Wk1  = (const float*)d_in[5];
    const float* Wq2  = (const float*)d_in[6];
    const float* Wk2  = (const float*)d_in[7];
    const float* FC1W = (const float*)d_in[8];
    const float* FC1B = (const float*)d_in[9];
    const float* W2   = (const float*)d_in[10];
    const float* B2   = (const float*)d_in[11];
    const float* W3   = (const float*)d_in[12];
    const float* B3   = (const float*)d_in[13];

    const int smem_bytes = Gn * BV_STRIDE * sizeof(uint32_t);   // 40960
    static int smem_set = 0;
    if (!smem_set) {
        cudaFuncSetAttribute(mlp_mma, cudaFuncAttributeMaxDynamicSharedMemorySize, smem_bytes);
        smem_set = 1;
    }

    prep<<<dim3(4, Bn), 256>>>(h, pp, pd, rec, Wq1, Wk1, Wq2, Wk2, FC1W, FC1B);
    mlp_mma<<<dim3(Gn / 8, Bn), 256, smem_bytes>>>(W2, B2, W3, B3, (float*)d_out);
}